// round 16
// baseline (speedup 1.0000x reference)
#include <cuda_runtime.h>
#include <cuda_fp16.h>
#include <cstdint>

#define MDIM 81984   // B*V
#define VV   2562
#define HH   192
#define BB   32
#define KP_H 96      // k-pairs for K=192
#define KP_1 488     // k-pairs for layer1 (K=966 padded to 976)
#define NT_H 12
#define NT_1 61
#define WROWS (KP_1 + 12 * KP_H)
#define NROWB ((MDIM + 255) / 256)   // 321 row blocks
#define NTILES (3 * NROWB)           // 963 tiles
#define PGRID 296                    // persistent blocks (148 SM x 2)

// ---------------- scratch (device globals) ----------------------------------
static __device__ uint32_t g_Sside[(size_t)MDIM * 32];  // GEMM out cols 0..63 (pre-scaled), half2
static __device__ uint32_t g_Ssup [(size_t)MDIM * 64];  // GEMM out cols 64..191, half2
static __device__ uint32_t g_Xp [(size_t)MDIM * KP_H];  // X fp16 pairs
static __device__ uint32_t g_Fp [(size_t)MDIM * KP_H];  // feats fp16 pairs (only feats copy)
static __device__ uint32_t g_A1p[(size_t)MDIM * KP_1];  // layer1 concat fp16 pairs
static __device__ uint32_t g_W  [(size_t)WROWS * HH];   // weight fp16 pairs [kpair][n]
static __device__ float    g_S3[(size_t)MDIM * 3];
static __device__ int      g_nbr[VV * 8];
static __device__ float    g_w [VV * 8];
static __device__ int      g_cnt[VV];
static __device__ float    g_invdeg[VV];

// ---------------- helpers ----------------------------------------------------
__device__ __forceinline__ uint32_t packh2(float x0, float x1) {
    __half2 h = __floats2half2_rn(x0, x1);
    return *reinterpret_cast<uint32_t*>(&h);
}
__device__ __forceinline__ float2 unpackh2(uint32_t u) {
    __half2 h = *reinterpret_cast<__half2*>(&u);
    return __half22float2(h);
}

__device__ __forceinline__ void mma16(float* c, const uint32_t* a, const uint32_t* b) {
    asm volatile(
        "mma.sync.aligned.m16n8k16.row.col.f32.f16.f16.f32 "
        "{%0,%1,%2,%3}, {%4,%5,%6,%7}, {%8,%9}, {%0,%1,%2,%3};\n"
        : "+f"(c[0]), "+f"(c[1]), "+f"(c[2]), "+f"(c[3])
        : "r"(a[0]), "r"(a[1]), "r"(a[2]), "r"(a[3]), "r"(b[0]), "r"(b[1]));
}

__device__ __forceinline__ void ldsm4(uint32_t* r, uint32_t addr) {
    asm volatile("ldmatrix.sync.aligned.m8n8.x4.shared.b16 {%0,%1,%2,%3}, [%4];\n"
        : "=r"(r[0]), "=r"(r[1]), "=r"(r[2]), "=r"(r[3]) : "r"(addr));
}

__device__ __forceinline__ uint32_t smem_u32(const void* p) {
    return (uint32_t)__cvta_generic_to_shared(p);
}
__device__ __forceinline__ void cpa16(uint32_t dst, const void* src, int sz) {
    asm volatile("cp.async.cg.shared.global [%0], [%1], 16, %2;\n"
                 :: "r"(dst), "l"(src), "r"(sz));
}

// ---------------- adjacency extraction ---------------------------------------
__global__ __launch_bounds__(256) void adj_kernel(const float* __restrict__ adj) {
    int u = blockIdx.x * (blockDim.x / 32) + (threadIdx.x / 32);
    int lane = threadIdx.x & 31;
    if (u >= VV) return;
    int cnt = 0;
    float deg = 0.f;
    for (int base = 0; base < VV; base += 32) {
        int v = base + lane;
        float f = (v < VV) ? adj[(size_t)u * VV + v] : 0.f;
        unsigned mask = __ballot_sync(0xffffffffu, f != 0.f);
        deg += f;
        if (f != 0.f) {
            int pos = cnt + __popc(mask & ((1u << lane) - 1u));
            if (pos < 8) { g_nbr[u * 8 + pos] = v; g_w[u * 8 + pos] = f; }
        }
        cnt += __popc(mask);
    }
    #pragma unroll
    for (int o = 16; o > 0; o >>= 1) deg += __shfl_down_sync(0xffffffffu, deg, o);
    if (lane == 0) {
        g_cnt[u] = cnt < 8 ? cnt : 8;
        g_invdeg[u] = 1.f / deg;
    }
}

// ---------------- weight pack (single fp16 plane): W1 + Wm -------------------
__global__ __launch_bounds__(256) void prep_w_kernel(const float* __restrict__ W1,
                                                     const float* __restrict__ Wm) {
    int idx = blockIdx.x * 256 + threadIdx.x;
    if (idx >= WROWS * HH) return;
    int kp = idx / HH, n = idx % HH;
    float x0, x1;
    if (kp < KP_1) {
        int k = 2 * kp;
        x0 = (k < 966)     ? W1[(size_t)k * HH + n]       : 0.f;
        x1 = (k + 1 < 966) ? W1[(size_t)(k + 1) * HH + n] : 0.f;
    } else {
        int r = kp - KP_1;
        int mat = r / KP_H, kpp = r % KP_H;
        int k = 2 * kpp;
        const float* Wb = Wm + (size_t)mat * HH * HH;
        x0 = Wb[(size_t)k * HH + n];
        x1 = Wb[(size_t)(k + 1) * HH + n];
    }
    g_W[idx] = packh2(x0, x1);
}

// ---------------- layer1 input pack: concat(F3,P) -> g_A1p (4 pairs/thread) --
__global__ __launch_bounds__(256) void prep_a1_kernel(const float* __restrict__ F3,
                                                      const float* __restrict__ P) {
    size_t q = (size_t)blockIdx.x * 256 + threadIdx.x;     // quad index
    if (q >= (size_t)MDIM * (KP_1 / 4)) return;
    int m  = (int)(q / (KP_1 / 4));
    int k4 = (int)(q % (KP_1 / 4));
    int kp0 = k4 * 4;
    uint32_t out[4];
    if (kp0 == 0) {
        float x[8];
        x[0] = F3[m * 3 + 0]; x[1] = F3[m * 3 + 1]; x[2] = F3[m * 3 + 2];
        #pragma unroll
        for (int i = 3; i < 8; i++) x[i] = P[(size_t)m * 963 + (i - 3)];
        #pragma unroll
        for (int j = 0; j < 4; j++) out[j] = packh2(x[2 * j], x[2 * j + 1]);
    } else {
        const float* p = P + (size_t)m * 963 + (2 * kp0 - 3);
        float x[8];
        #pragma unroll
        for (int i = 0; i < 8; i++) {
            int c = 2 * kp0 + i;
            x[i] = (c < 966) ? p[i] : 0.f;
        }
        #pragma unroll
        for (int j = 0; j < 4; j++) out[j] = packh2(x[2 * j], x[2 * j + 1]);
    }
    *reinterpret_cast<uint4*>(&g_A1p[(size_t)m * KP_1 + kp0]) =
        make_uint4(out[0], out[1], out[2], out[3]);
}

// ---------------- persistent fp16 tensor-core GEMM ----------------------------
// 296 blocks loop over 963 tiles (block tile 256x64, warp tile 64x32).
// R11 mainloop per tile; loads beyond NT are skipped (not zero-sized).
__global__ __launch_bounds__(256, 2) void gemm_f16_kernel(int asel, int woff, int NT) {
    __shared__ uint32_t As[4][256][8];      // swizzled: col ^= ((row>>2)&1)*4
    __shared__ uint32_t Bs[4][8][72];       // [stage][kpair][n], padded

    const uint32_t* Ap; int akp;
    if (asel == 0)      { Ap = g_Xp;  akp = KP_H; }
    else if (asel == 1) { Ap = g_Fp;  akp = KP_H; }
    else                { Ap = g_A1p; akp = KP_1; }

    int t = threadIdx.x, lane = t & 31, warp = t >> 5;
    int wm = (warp >> 1) * 64, wn = (warp & 1) * 32;
    int g = lane >> 2, t4 = lane & 3;
    int b_kp = t >> 4, b_n4 = (t & 15) * 4;
    int lm_row = lane & 15;
    int lm_k4  = (lane >> 4) * 4;

    for (int tile = blockIdx.x; tile < NTILES; tile += PGRID) {
        int rowBase = (tile / 3) * 256;
        int colBase = (tile % 3) * 64;

        float acc[4][4][4];
        #pragma unroll
        for (int mt = 0; mt < 4; mt++)
            #pragma unroll
            for (int nt = 0; nt < 4; nt++)
                #pragma unroll
                for (int i = 0; i < 4; i++) acc[mt][nt][i] = 0.f;

        auto load_stage = [&](int kt) {
            if (kt < NT) {
                int s = kt & 3;
                int k0p = kt * 8;
                #pragma unroll
                for (int i = 0; i < 2; i++) {
                    int c = t + i * 256;
                    int row = c >> 1, half = c & 1;
                    int gm = rowBase + row;
                    int dcol = (half * 4) ^ (((row >> 2) & 1) * 4);
                    cpa16(smem_u32(&As[s][row][dcol]),
                          Ap + (size_t)gm * akp + k0p + half * 4,
                          (gm < MDIM) ? 16 : 0);
                }
                if (t < 128)
                    cpa16(smem_u32(&Bs[s][b_kp][b_n4]),
                          g_W + (size_t)(woff + k0p + b_kp) * HH + colBase + b_n4,
                          16);
            }
            asm volatile("cp.async.commit_group;\n");
        };

        load_stage(0);
        load_stage(1);
        load_stage(2);

        for (int kt = 0; kt < NT; kt++) {
            asm volatile("cp.async.wait_group %0;\n" :: "n"(2));
            __syncthreads();

            int s = kt & 3;
            uint32_t a[4][4];
            #pragma unroll
            for (int mt = 0; mt < 4; mt++) {
                int row = wm + mt * 16 + lm_row;
                int col = lm_k4 ^ (((row >> 2) & 1) * 4);
                ldsm4(a[mt], smem_u32(&As[s][row][col]));
            }
            #pragma unroll
            for (int nt = 0; nt < 4; nt++) {
                int cn = wn + nt * 8 + g;
                uint32_t b[2] = { Bs[s][t4][cn], Bs[s][t4 + 4][cn] };
                #pragma unroll
                for (int mt = 0; mt < 4; mt++)
                    mma16(acc[mt][nt], a[mt], b);
            }
            __syncthreads();
            load_stage(kt + 3);
        }

        // ---- epilogue: pack half2; side (cols<64) scaled -> g_Sside; else g_Ssup ----
        #pragma unroll
        for (int mt = 0; mt < 4; mt++) {
            int gm0 = rowBase + wm + mt * 16 + g;
            #pragma unroll
            for (int nt = 0; nt < 4; nt++) {
                int gc = colBase + wn + nt * 8 + t4 * 2;
                int cp = gc >> 1;
                bool side = (gc < 64);
                if (gm0 < MDIM) {
                    if (side) {
                        float sc = g_invdeg[gm0 % VV];
                        g_Sside[(size_t)gm0 * 32 + cp] = packh2(acc[mt][nt][0] * sc, acc[mt][nt][1] * sc);
                    } else {
                        g_Ssup[(size_t)gm0 * 64 + cp - 32] = packh2(acc[mt][nt][0], acc[mt][nt][1]);
                    }
                }
                int gm1 = gm0 + 8;
                if (gm1 < MDIM) {
                    if (side) {
                        float sc = g_invdeg[gm1 % VV];
                        g_Sside[(size_t)gm1 * 32 + cp] = packh2(acc[mt][nt][2] * sc, acc[mt][nt][3] * sc);
                    } else {
                        g_Ssup[(size_t)gm1 * 64 + cp - 32] = packh2(acc[mt][nt][2], acc[mt][nt][3]);
                    }
                }
            }
        }
        __syncthreads();   // epilogue reads of As done before next tile overwrites
    }
}

// ---------------- fused combine + BN stats + apply (per vertex, R15) ---------
__global__ __launch_bounds__(256) void post_kernel(
    const float* __restrict__ bias,
    const float* __restrict__ gam, const float* __restrict__ bet,
    const float* __restrict__ F3, const float* __restrict__ P,
    float* __restrict__ dout, int mode)
{
    int v = blockIdx.x, t = threadIdx.x;
    __shared__ __align__(16) float ybuf[BB * HH];   // [b][c]
    __shared__ float sbias[HH];
    __shared__ int   s_nbr[8];
    __shared__ float s_w[8];
    __shared__ int   s_cnt;
    __shared__ float redS[8], redQ[8];
    __shared__ float s_mean, s_istd;

    if (t < 8) { s_nbr[t] = g_nbr[v * 8 + t]; s_w[t] = g_w[v * 8 + t]; }
    if (t == 0) s_cnt = g_cnt[v];
    if (t < HH) sbias[t] = bias[t];
    __syncthreads();
    int cnt = s_cnt;

    float s = 0.f, ss = 0.f;

    // ---- support: 1024 uint2 (4 channels each), 4 per thread ----
    #pragma unroll
    for (int it = 0; it < 4; it++) {
        int idx = t + it * 256;
        int b = idx >> 5, cpq = idx & 31;
        int cp0 = 2 * cpq;
        int c = 2 * cp0;
        uint2 U = *reinterpret_cast<const uint2*>(
            &g_Ssup[((size_t)(b * VV + v)) * 64 + cp0]);
        float2 p0 = unpackh2(U.x), p1 = unpackh2(U.y);
        float y0 = p0.x + sbias[c],     y1 = p0.y + sbias[c + 1];
        float y2 = p1.x + sbias[c + 2], y3 = p1.y + sbias[c + 3];
        *reinterpret_cast<float4*>(&ybuf[b * HH + c]) = make_float4(y0, y1, y2, y3);
        s += (y0 + y1) + (y2 + y3);
        ss += (y0 * y0 + y1 * y1) + (y2 * y2 + y3 * y3);
    }

    // ---- gather: 1024 pairs, 4 per thread; j-outer, q-inner (MLP 4) ----
    {
        float a0[4], a1[4];
        int off[4];
        #pragma unroll
        for (int q = 0; q < 4; q++) {
            int idx = t + q * 256;
            int b = idx >> 5, dp = idx & 31;
            off[q] = b * (VV * 32) + dp;
            a0[q] = 0.f; a1[q] = 0.f;
        }
        for (int j = 0; j < cnt; j++) {
            int nb32 = s_nbr[j] * 32;
            float w = s_w[j];
            #pragma unroll
            for (int q = 0; q < 4; q++) {
                float2 p = unpackh2(g_Sside[(size_t)(off[q] + nb32)]);
                a0[q] += w * p.x; a1[q] += w * p.y;
            }
        }
        #pragma unroll
        for (int q = 0; q < 4; q++) {
            int idx = t + q * 256;
            int b = idx >> 5, dp = idx & 31;
            int c = 128 + 2 * dp;
            float y0 = a0[q] + sbias[c];
            float y1 = a1[q] + sbias[c + 1];
            ybuf[b * HH + c] = y0; ybuf[b * HH + c + 1] = y1;
            s += y0 + y1; ss += y0 * y0 + y1 * y1;
        }
    }

    // ---- block reduction ----
    #pragma unroll
    for (int o = 16; o > 0; o >>= 1) {
        s  += __shfl_down_sync(0xffffffffu, s, o);
        ss += __shfl_down_sync(0xffffffffu, ss, o);
    }
    int lane = t & 31, warp = t >> 5;
    if (lane == 0) { redS[warp] = s; redQ[warp] = ss; }
    __syncthreads();
    if (t == 0) {
        float S = 0.f, Q = 0.f;
        #pragma unroll
        for (int w = 0; w < 8; w++) { S += redS[w]; Q += redQ[w]; }
        float n = (float)(BB * HH);
        float mu = S / n;
        s_mean = mu;
        s_istd = rsqrtf(Q / n - mu * mu + 1e-5f);
    }
    __syncthreads();

    // ---- apply: 1536 quad-channels (float4), 6 per thread ----
    float gv = gam[v], bv = bet[v], mu = s_mean, istd = s_istd;
    #pragma unroll
    for (int it = 0; it < 6; it++) {
        int pp = t + it * 256;
        int b = pp / 48, q = pp - b * 48;
        int cp0 = 2 * q;
        int c = 2 * cp0;
        int m = b * VV + v;
        float4 Y = *reinterpret_cast<const float4*>(&ybuf[b * HH + c]);
        float y0 = fmaxf(gv * (Y.x - mu) * istd + bv, 0.f);
        float y1 = fmaxf(gv * (Y.y - mu) * istd + bv, 0.f);
        float y2 = fmaxf(gv * (Y.z - mu) * istd + bv, 0.f);
        float y3 = fmaxf(gv * (Y.w - mu) * istd + bv, 0.f);
        size_t pidx = (size_t)m * KP_H + cp0;
        if (mode == 0) {
            *reinterpret_cast<uint2*>(&g_Xp[pidx]) =
                make_uint2(packh2(y0, y1), packh2(y2, y3));
        } else {
            float r0, r1, r2, r3;
            if (mode == 1) {
                float b0, b1, b2, b3;
                if (c == 0) {
                    b0 = F3[m * 3 + 0]; b1 = F3[m * 3 + 1]; b2 = F3[m * 3 + 2];
                    b3 = P[(size_t)m * 963 + 0];
                } else {
                    const float* p = P + (size_t)m * 963 + (c - 3);
                    b0 = p[0]; b1 = p[1]; b2 = p[2]; b3 = p[3];
                }
                r0 = (b0 + y0) * 0.5f; r1 = (b1 + y1) * 0.5f;
                r2 = (b2 + y2) * 0.5f; r3 = (b3 + y3) * 0.5f;
            } else {
                uint2 F = *reinterpret_cast<const uint2*>(&g_Fp[pidx]);
                float2 f0 = unpackh2(F.x), f1 = unpackh2(F.y);
                r0 = (f0.x + y0) * 0.5f; r1 = (f0.y + y1) * 0.5f;
                r2 = (f1.x + y2) * 0.5f; r3 = (f1.y + y3) * 0.5f;
            }
            *reinterpret_cast<uint2*>(&g_Fp[pidx]) =
                make_uint2(packh2(r0, r1), packh2(r2, r3));
            if (mode == 3)
                *reinterpret_cast<float4*>(&dout[(size_t)m * HH + c]) =
                    make_float4(r0, r1, r2, r3);
        }
    }
}

// ---------------- head GEMM: S3 = feats @ W15, cols<2 pre-scaled -------------
__global__ __launch_bounds__(256) void gemm3_kernel(const float* __restrict__ W15) {
    int warp = (blockIdx.x * blockDim.x + threadIdx.x) >> 5;
    int lane = threadIdx.x & 31;
    if (warp >= MDIM) return;
    const uint32_t* row = g_Fp + (size_t)warp * KP_H;
    float a0 = 0.f, a1 = 0.f, a2 = 0.f;
    for (int kp = lane; kp < KP_H; kp += 32) {
        float2 f = unpackh2(row[kp]);
        int k = 2 * kp;
        a0 = fmaf(f.x, W15[k * 3 + 0], a0);
        a1 = fmaf(f.x, W15[k * 3 + 1], a1);
        a2 = fmaf(f.x, W15[k * 3 + 2], a2);
        a0 = fmaf(f.y, W15[k * 3 + 3], a0);
        a1 = fmaf(f.y, W15[k * 3 + 4], a1);
        a2 = fmaf(f.y, W15[k * 3 + 5], a2);
    }
    #pragma unroll
    for (int o = 16; o > 0; o >>= 1) {
        a0 += __shfl_down_sync(0xffffffffu, a0, o);
        a1 += __shfl_down_sync(0xffffffffu, a1, o);
        a2 += __shfl_down_sync(0xffffffffu, a2, o);
    }
    if (lane == 0) {
        float inv = g_invdeg[warp % VV];
        g_S3[warp * 3 + 0] = a0 * inv;
        g_S3[warp * 3 + 1] = a1 * inv;
        g_S3[warp * 3 + 2] = a2;
    }
}

__global__ __launch_bounds__(256) void coords_kernel(float* __restrict__ dout,
                                                     const float* __restrict__ b15) {
    int m = blockIdx.x * blockDim.x + threadIdx.x;
    if (m >= MDIM) return;
    int v = m % VV, b = m / VV;
    float s0 = 0.f, s1 = 0.f;
    int cnt = g_cnt[v];
    for (int j = 0; j < cnt; j++) {
        int nv = g_nbr[v * 8 + j];
        float w = g_w[v * 8 + j];
        const float* p = g_S3 + (size_t)(b * VV + nv) * 3;
        s0 += w * p[0];
        s1 += w * p[1];
    }
    float* o = dout + (size_t)MDIM * HH + (size_t)m * 3;
    o[0] = g_S3[m * 3 + 2] + b15[0];
    o[1] = s0 + b15[1];
    o[2] = s1 + b15[2];
}

// ---------------- driver ----------------------------------------------------
extern "C" void kernel_launch(void* const* d_in, const int* in_sizes, int n_in,
                              void* d_out, int out_size) {
    const float* features = (const float*)d_in[0];
    const float* pooled   = (const float*)d_in[1];
    const float* adj      = (const float*)d_in[2];
    const float* W1       = (const float*)d_in[3];
    const float* b1       = (const float*)d_in[4];
    const float* Wm       = (const float*)d_in[5];
    const float* bm       = (const float*)d_in[6];
    const float* W15      = (const float*)d_in[7];
    const float* b15      = (const float*)d_in[8];
    const float* gamma    = (const float*)d_in[9];
    const float* beta     = (const float*)d_in[10];
    float* dout = (float*)d_out;

    adj_kernel<<<(VV + 7) / 8, 256>>>(adj);
    prep_w_kernel<<<(WROWS * HH + 255) / 256, 256>>>(W1, Wm);
    prep_a1_kernel<<<(int)(((size_t)MDIM * (KP_1 / 4) + 255) / 256), 256>>>(features, pooled);

    // layer 1
    gemm_f16_kernel<<<PGRID, 256>>>(2, 0, NT_1);
    post_kernel<<<VV, 256>>>(b1, gamma + 0 * VV, beta + 0 * VV, features, pooled, dout, 0);

    // layer 2
    gemm_f16_kernel<<<PGRID, 256>>>(0, KP_1 + 0 * KP_H, NT_H);
    post_kernel<<<VV, 256>>>(bm + 0 * HH, gamma + 1 * VV, beta + 1 * VV, features, pooled, dout, 1);

    for (int i = 0; i < 5; i++) {
        int wa = 2 * i + 1, wb = 2 * i + 2;
        gemm_f16_kernel<<<PGRID, 256>>>(1, KP_1 + wa * KP_H, NT_H);
        post_kernel<<<VV, 256>>>(bm + wa * HH, gamma + (2 * i + 2) * VV, beta + (2 * i + 2) * VV,
                                 features, pooled, dout, 0);
        gemm_f16_kernel<<<PGRID, 256>>>(0, KP_1 + wb * KP_H, NT_H);
        post_kernel<<<VV, 256>>>(bm + wb * HH, gamma + (2 * i + 3) * VV, beta + (2 * i + 3) * VV,
                                 features, pooled, dout, 2);
    }

    // layer 13
    gemm_f16_kernel<<<PGRID, 256>>>(1, KP_1 + 11 * KP_H, NT_H);
    post_kernel<<<VV, 256>>>(bm + 11 * HH, gamma + 12 * VV, beta + 12 * VV, features, pooled, dout, 3);

    gemm3_kernel<<<(MDIM * 32 + 255) / 256, 256>>>(W15);
    coords_kernel<<<(MDIM + 255) / 256, 256>>>(dout, b15);
}

// round 17
// speedup vs baseline: 1.0121x; 1.0121x over previous
#include <cuda_runtime.h>
#include <cuda_fp16.h>
#include <cstdint>

#define MDIM 81984   // B*V
#define VV   2562
#define HH   192
#define BB   32
#define KP_H 96      // k-pairs for K=192
#define KP_1 488     // k-pairs for layer1 (K=966 padded to 976)
#define NT_H 12
#define NT_1 61
#define WROWS (KP_1 + 12 * KP_H)

// ---------------- scratch (device globals) ----------------------------------
static __device__ uint32_t g_Sside[(size_t)MDIM * 32];  // GEMM out cols 0..63 (pre-scaled), half2
static __device__ uint32_t g_Ssup [(size_t)MDIM * 64];  // GEMM out cols 64..191, half2
static __device__ uint32_t g_Xp [(size_t)MDIM * KP_H];  // X fp16 pairs
static __device__ uint32_t g_Fp [(size_t)MDIM * KP_H];  // feats fp16 pairs (only feats copy)
static __device__ uint32_t g_A1p[(size_t)MDIM * KP_1];  // layer1 concat fp16 pairs
static __device__ uint32_t g_W  [(size_t)WROWS * HH];   // weight fp16 pairs [kpair][n]
static __device__ float    g_S3[(size_t)MDIM * 3];
static __device__ int      g_nbr[VV * 8];
static __device__ float    g_w [VV * 8];
static __device__ int      g_cnt[VV];
static __device__ float    g_invdeg[VV];

// ---------------- helpers ----------------------------------------------------
__device__ __forceinline__ uint32_t packh2(float x0, float x1) {
    __half2 h = __floats2half2_rn(x0, x1);
    return *reinterpret_cast<uint32_t*>(&h);
}
__device__ __forceinline__ float2 unpackh2(uint32_t u) {
    __half2 h = *reinterpret_cast<__half2*>(&u);
    return __half22float2(h);
}

__device__ __forceinline__ void mma16(float* c, const uint32_t* a, const uint32_t* b) {
    asm volatile(
        "mma.sync.aligned.m16n8k16.row.col.f32.f16.f16.f32 "
        "{%0,%1,%2,%3}, {%4,%5,%6,%7}, {%8,%9}, {%0,%1,%2,%3};\n"
        : "+f"(c[0]), "+f"(c[1]), "+f"(c[2]), "+f"(c[3])
        : "r"(a[0]), "r"(a[1]), "r"(a[2]), "r"(a[3]), "r"(b[0]), "r"(b[1]));
}

__device__ __forceinline__ void ldsm4(uint32_t* r, uint32_t addr) {
    asm volatile("ldmatrix.sync.aligned.m8n8.x4.shared.b16 {%0,%1,%2,%3}, [%4];\n"
        : "=r"(r[0]), "=r"(r[1]), "=r"(r[2]), "=r"(r[3]) : "r"(addr));
}

__device__ __forceinline__ uint32_t smem_u32(const void* p) {
    return (uint32_t)__cvta_generic_to_shared(p);
}
__device__ __forceinline__ void cpa16(uint32_t dst, const void* src, int sz) {
    asm volatile("cp.async.cg.shared.global [%0], [%1], 16, %2;\n"
                 :: "r"(dst), "l"(src), "r"(sz));
}

// ---------------- adjacency extraction ---------------------------------------
__global__ __launch_bounds__(256) void adj_kernel(const float* __restrict__ adj) {
    int u = blockIdx.x * (blockDim.x / 32) + (threadIdx.x / 32);
    int lane = threadIdx.x & 31;
    if (u >= VV) return;
    int cnt = 0;
    float deg = 0.f;
    for (int base = 0; base < VV; base += 32) {
        int v = base + lane;
        float f = (v < VV) ? adj[(size_t)u * VV + v] : 0.f;
        unsigned mask = __ballot_sync(0xffffffffu, f != 0.f);
        deg += f;
        if (f != 0.f) {
            int pos = cnt + __popc(mask & ((1u << lane) - 1u));
            if (pos < 8) { g_nbr[u * 8 + pos] = v; g_w[u * 8 + pos] = f; }
        }
        cnt += __popc(mask);
    }
    #pragma unroll
    for (int o = 16; o > 0; o >>= 1) deg += __shfl_down_sync(0xffffffffu, deg, o);
    if (lane == 0) {
        g_cnt[u] = cnt < 8 ? cnt : 8;
        g_invdeg[u] = 1.f / deg;
    }
}

// ---------------- weight pack (single fp16 plane): W1 + Wm -------------------
__global__ __launch_bounds__(256) void prep_w_kernel(const float* __restrict__ W1,
                                                     const float* __restrict__ Wm) {
    int idx = blockIdx.x * 256 + threadIdx.x;
    if (idx >= WROWS * HH) return;
    int kp = idx / HH, n = idx % HH;
    float x0, x1;
    if (kp < KP_1) {
        int k = 2 * kp;
        x0 = (k < 966)     ? W1[(size_t)k * HH + n]       : 0.f;
        x1 = (k + 1 < 966) ? W1[(size_t)(k + 1) * HH + n] : 0.f;
    } else {
        int r = kp - KP_1;
        int mat = r / KP_H, kpp = r % KP_H;
        int k = 2 * kpp;
        const float* Wb = Wm + (size_t)mat * HH * HH;
        x0 = Wb[(size_t)k * HH + n];
        x1 = Wb[(size_t)(k + 1) * HH + n];
    }
    g_W[idx] = packh2(x0, x1);
}

// ---------------- layer1 input pack: concat(F3,P) -> g_A1p (4 pairs/thread) --
__global__ __launch_bounds__(256) void prep_a1_kernel(const float* __restrict__ F3,
                                                      const float* __restrict__ P) {
    size_t q = (size_t)blockIdx.x * 256 + threadIdx.x;     // quad index
    if (q >= (size_t)MDIM * (KP_1 / 4)) return;
    int m  = (int)(q / (KP_1 / 4));
    int k4 = (int)(q % (KP_1 / 4));
    int kp0 = k4 * 4;
    uint32_t out[4];
    if (kp0 == 0) {
        float x[8];
        x[0] = F3[m * 3 + 0]; x[1] = F3[m * 3 + 1]; x[2] = F3[m * 3 + 2];
        #pragma unroll
        for (int i = 3; i < 8; i++) x[i] = P[(size_t)m * 963 + (i - 3)];
        #pragma unroll
        for (int j = 0; j < 4; j++) out[j] = packh2(x[2 * j], x[2 * j + 1]);
    } else {
        const float* p = P + (size_t)m * 963 + (2 * kp0 - 3);
        float x[8];
        #pragma unroll
        for (int i = 0; i < 8; i++) {
            int c = 2 * kp0 + i;
            x[i] = (c < 966) ? p[i] : 0.f;
        }
        #pragma unroll
        for (int j = 0; j < 4; j++) out[j] = packh2(x[2 * j], x[2 * j + 1]);
    }
    *reinterpret_cast<uint4*>(&g_A1p[(size_t)m * KP_1 + kp0]) =
        make_uint4(out[0], out[1], out[2], out[3]);
}

// ---------------- fp16 tensor-core GEMM (frozen R11/R15 form) -----------------
__global__ __launch_bounds__(256, 2) void gemm_f16_kernel(int asel, int woff, int NT) {
    __shared__ uint32_t As[4][256][8];      // swizzled: col ^= ((row>>2)&1)*4
    __shared__ uint32_t Bs[4][8][72];       // [stage][kpair][n], padded

    const uint32_t* Ap; int akp;
    if (asel == 0)      { Ap = g_Xp;  akp = KP_H; }
    else if (asel == 1) { Ap = g_Fp;  akp = KP_H; }
    else                { Ap = g_A1p; akp = KP_1; }

    int t = threadIdx.x, lane = t & 31, warp = t >> 5;
    int wm = (warp >> 1) * 64, wn = (warp & 1) * 32;
    int g = lane >> 2, t4 = lane & 3;
    int rowBase = blockIdx.y * 256, colBase = blockIdx.x * 64;

    float acc[4][4][4];
    #pragma unroll
    for (int mt = 0; mt < 4; mt++)
        #pragma unroll
        for (int nt = 0; nt < 4; nt++)
            #pragma unroll
            for (int i = 0; i < 4; i++) acc[mt][nt][i] = 0.f;

    int b_kp = t >> 4, b_n4 = (t & 15) * 4;
    int lm_row = lane & 15;
    int lm_k4  = (lane >> 4) * 4;

    auto load_stage = [&](int kt) {
        int s = kt & 3;
        int k0p = kt * 8;
        int ok = (kt < NT) ? 16 : 0;
        #pragma unroll
        for (int i = 0; i < 2; i++) {
            int c = t + i * 256;
            int row = c >> 1, half = c & 1;
            int gm = rowBase + row;
            int dcol = (half * 4) ^ (((row >> 2) & 1) * 4);
            cpa16(smem_u32(&As[s][row][dcol]),
                  Ap + (size_t)gm * akp + k0p + half * 4,
                  (gm < MDIM) ? ok : 0);
        }
        if (t < 128)
            cpa16(smem_u32(&Bs[s][b_kp][b_n4]),
                  g_W + (size_t)(woff + k0p + b_kp) * HH + colBase + b_n4,
                  ok);
        asm volatile("cp.async.commit_group;\n");
    };

    load_stage(0);
    load_stage(1);
    load_stage(2);

    for (int kt = 0; kt < NT; kt++) {
        asm volatile("cp.async.wait_group %0;\n" :: "n"(2));
        __syncthreads();

        int s = kt & 3;
        uint32_t a[4][4];
        #pragma unroll
        for (int mt = 0; mt < 4; mt++) {
            int row = wm + mt * 16 + lm_row;
            int col = lm_k4 ^ (((row >> 2) & 1) * 4);
            ldsm4(a[mt], smem_u32(&As[s][row][col]));
        }
        #pragma unroll
        for (int nt = 0; nt < 4; nt++) {
            int cn = wn + nt * 8 + g;
            uint32_t b[2] = { Bs[s][t4][cn], Bs[s][t4 + 4][cn] };
            #pragma unroll
            for (int mt = 0; mt < 4; mt++)
                mma16(acc[mt][nt], a[mt], b);
        }
        __syncthreads();
        load_stage(kt + 3);
    }

    // ---- epilogue: pack half2; side (cols<64) scaled -> g_Sside; else g_Ssup ----
    #pragma unroll
    for (int mt = 0; mt < 4; mt++) {
        int gm0 = rowBase + wm + mt * 16 + g;
        #pragma unroll
        for (int nt = 0; nt < 4; nt++) {
            int gc = colBase + wn + nt * 8 + t4 * 2;
            int cp = gc >> 1;
            bool side = (gc < 64);
            if (gm0 < MDIM) {
                if (side) {
                    float sc = g_invdeg[gm0 % VV];
                    g_Sside[(size_t)gm0 * 32 + cp] = packh2(acc[mt][nt][0] * sc, acc[mt][nt][1] * sc);
                } else {
                    g_Ssup[(size_t)gm0 * 64 + cp - 32] = packh2(acc[mt][nt][0], acc[mt][nt][1]);
                }
            }
            int gm1 = gm0 + 8;
            if (gm1 < MDIM) {
                if (side) {
                    float sc = g_invdeg[gm1 % VV];
                    g_Sside[(size_t)gm1 * 32 + cp] = packh2(acc[mt][nt][2] * sc, acc[mt][nt][3] * sc);
                } else {
                    g_Ssup[(size_t)gm1 * 64 + cp - 32] = packh2(acc[mt][nt][2], acc[mt][nt][3]);
                }
            }
        }
    }
}

// ---------------- fused combine + BN stats + apply (per vertex) --------------
// gather: dynamic j-loop unrolled by 2 (8 loads in flight per step)
__global__ __launch_bounds__(256) void post_kernel(
    const float* __restrict__ bias,
    const float* __restrict__ gam, const float* __restrict__ bet,
    const float* __restrict__ F3, const float* __restrict__ P,
    float* __restrict__ dout, int mode)
{
    int v = blockIdx.x, t = threadIdx.x;
    __shared__ __align__(16) float ybuf[BB * HH];   // [b][c]
    __shared__ float sbias[HH];
    __shared__ int   s_nbr[8];
    __shared__ float s_w[8];
    __shared__ int   s_cnt;
    __shared__ float redS[8], redQ[8];
    __shared__ float s_mean, s_istd;

    if (t < 8) { s_nbr[t] = g_nbr[v * 8 + t]; s_w[t] = g_w[v * 8 + t]; }
    if (t == 0) s_cnt = g_cnt[v];
    if (t < HH) sbias[t] = bias[t];
    __syncthreads();
    int cnt = s_cnt;

    float s = 0.f, ss = 0.f;

    // ---- support: 1024 uint2 (4 channels each), 4 per thread ----
    #pragma unroll
    for (int it = 0; it < 4; it++) {
        int idx = t + it * 256;
        int b = idx >> 5, cpq = idx & 31;
        int cp0 = 2 * cpq;
        int c = 2 * cp0;
        uint2 U = *reinterpret_cast<const uint2*>(
            &g_Ssup[((size_t)(b * VV + v)) * 64 + cp0]);
        float2 p0 = unpackh2(U.x), p1 = unpackh2(U.y);
        float y0 = p0.x + sbias[c],     y1 = p0.y + sbias[c + 1];
        float y2 = p1.x + sbias[c + 2], y3 = p1.y + sbias[c + 3];
        *reinterpret_cast<float4*>(&ybuf[b * HH + c]) = make_float4(y0, y1, y2, y3);
        s += (y0 + y1) + (y2 + y3);
        ss += (y0 * y0 + y1 * y1) + (y2 * y2 + y3 * y3);
    }

    // ---- gather: 1024 pairs, 4 per thread; j unrolled by 2 (MLP 8) ----
    {
        float a0[4], a1[4];
        int off[4];
        #pragma unroll
        for (int q = 0; q < 4; q++) {
            int idx = t + q * 256;
            int b = idx >> 5, dp = idx & 31;
            off[q] = b * (VV * 32) + dp;
            a0[q] = 0.f; a1[q] = 0.f;
        }
        int j = 0;
        for (; j + 2 <= cnt; j += 2) {
            int nbA = s_nbr[j] * 32, nbB = s_nbr[j + 1] * 32;
            float wA = s_w[j], wB = s_w[j + 1];
            uint32_t uA[4], uB[4];
            #pragma unroll
            for (int q = 0; q < 4; q++) {
                uA[q] = g_Sside[(size_t)(off[q] + nbA)];
                uB[q] = g_Sside[(size_t)(off[q] + nbB)];
            }
            #pragma unroll
            for (int q = 0; q < 4; q++) {
                float2 pA = unpackh2(uA[q]), pB = unpackh2(uB[q]);
                a0[q] += wA * pA.x + wB * pB.x;
                a1[q] += wA * pA.y + wB * pB.y;
            }
        }
        if (j < cnt) {
            int nb = s_nbr[j] * 32;
            float w = s_w[j];
            #pragma unroll
            for (int q = 0; q < 4; q++) {
                float2 p = unpackh2(g_Sside[(size_t)(off[q] + nb)]);
                a0[q] += w * p.x; a1[q] += w * p.y;
            }
        }
        #pragma unroll
        for (int q = 0; q < 4; q++) {
            int idx = t + q * 256;
            int b = idx >> 5, dp = idx & 31;
            int c = 128 + 2 * dp;
            float y0 = a0[q] + sbias[c];
            float y1 = a1[q] + sbias[c + 1];
            ybuf[b * HH + c] = y0; ybuf[b * HH + c + 1] = y1;
            s += y0 + y1; ss += y0 * y0 + y1 * y1;
        }
    }

    // ---- block reduction ----
    #pragma unroll
    for (int o = 16; o > 0; o >>= 1) {
        s  += __shfl_down_sync(0xffffffffu, s, o);
        ss += __shfl_down_sync(0xffffffffu, ss, o);
    }
    int lane = t & 31, warp = t >> 5;
    if (lane == 0) { redS[warp] = s; redQ[warp] = ss; }
    __syncthreads();
    if (t == 0) {
        float S = 0.f, Q = 0.f;
        #pragma unroll
        for (int w = 0; w < 8; w++) { S += redS[w]; Q += redQ[w]; }
        float n = (float)(BB * HH);
        float mu = S / n;
        s_mean = mu;
        s_istd = rsqrtf(Q / n - mu * mu + 1e-5f);
    }
    __syncthreads();

    // ---- apply: 1536 quad-channels (float4), 6 per thread ----
    float gv = gam[v], bv = bet[v], mu = s_mean, istd = s_istd;
    #pragma unroll
    for (int it = 0; it < 6; it++) {
        int pp = t + it * 256;
        int b = pp / 48, q = pp - b * 48;
        int cp0 = 2 * q;
        int c = 2 * cp0;
        int m = b * VV + v;
        float4 Y = *reinterpret_cast<const float4*>(&ybuf[b * HH + c]);
        float y0 = fmaxf(gv * (Y.x - mu) * istd + bv, 0.f);
        float y1 = fmaxf(gv * (Y.y - mu) * istd + bv, 0.f);
        float y2 = fmaxf(gv * (Y.z - mu) * istd + bv, 0.f);
        float y3 = fmaxf(gv * (Y.w - mu) * istd + bv, 0.f);
        size_t pidx = (size_t)m * KP_H + cp0;
        if (mode == 0) {
            *reinterpret_cast<uint2*>(&g_Xp[pidx]) =
                make_uint2(packh2(y0, y1), packh2(y2, y3));
        } else {
            float r0, r1, r2, r3;
            if (mode == 1) {
                float b0, b1, b2, b3;
                if (c == 0) {
                    b0 = F3[m * 3 + 0]; b1 = F3[m * 3 + 1]; b2 = F3[m * 3 + 2];
                    b3 = P[(size_t)m * 963 + 0];
                } else {
                    const float* p = P + (size_t)m * 963 + (c - 3);
                    b0 = p[0]; b1 = p[1]; b2 = p[2]; b3 = p[3];
                }
                r0 = (b0 + y0) * 0.5f; r1 = (b1 + y1) * 0.5f;
                r2 = (b2 + y2) * 0.5f; r3 = (b3 + y3) * 0.5f;
            } else {
                uint2 F = *reinterpret_cast<const uint2*>(&g_Fp[pidx]);
                float2 f0 = unpackh2(F.x), f1 = unpackh2(F.y);
                r0 = (f0.x + y0) * 0.5f; r1 = (f0.y + y1) * 0.5f;
                r2 = (f1.x + y2) * 0.5f; r3 = (f1.y + y3) * 0.5f;
            }
            *reinterpret_cast<uint2*>(&g_Fp[pidx]) =
                make_uint2(packh2(r0, r1), packh2(r2, r3));
            if (mode == 3)
                *reinterpret_cast<float4*>(&dout[(size_t)m * HH + c]) =
                    make_float4(r0, r1, r2, r3);
        }
    }
}

// ---------------- head GEMM: S3 = feats @ W15, cols<2 pre-scaled -------------
__global__ __launch_bounds__(256) void gemm3_kernel(const float* __restrict__ W15) {
    int warp = (blockIdx.x * blockDim.x + threadIdx.x) >> 5;
    int lane = threadIdx.x & 31;
    if (warp >= MDIM) return;
    const uint32_t* row = g_Fp + (size_t)warp * KP_H;
    float a0 = 0.f, a1 = 0.f, a2 = 0.f;
    for (int kp = lane; kp < KP_H; kp += 32) {
        float2 f = unpackh2(row[kp]);
        int k = 2 * kp;
        a0 = fmaf(f.x, W15[k * 3 + 0], a0);
        a1 = fmaf(f.x, W15[k * 3 + 1], a1);
        a2 = fmaf(f.x, W15[k * 3 + 2], a2);
        a0 = fmaf(f.y, W15[k * 3 + 3], a0);
        a1 = fmaf(f.y, W15[k * 3 + 4], a1);
        a2 = fmaf(f.y, W15[k * 3 + 5], a2);
    }
    #pragma unroll
    for (int o = 16; o > 0; o >>= 1) {
        a0 += __shfl_down_sync(0xffffffffu, a0, o);
        a1 += __shfl_down_sync(0xffffffffu, a1, o);
        a2 += __shfl_down_sync(0xffffffffu, a2, o);
    }
    if (lane == 0) {
        float inv = g_invdeg[warp % VV];
        g_S3[warp * 3 + 0] = a0 * inv;
        g_S3[warp * 3 + 1] = a1 * inv;
        g_S3[warp * 3 + 2] = a2;
    }
}

__global__ __launch_bounds__(256) void coords_kernel(float* __restrict__ dout,
                                                     const float* __restrict__ b15) {
    int m = blockIdx.x * blockDim.x + threadIdx.x;
    if (m >= MDIM) return;
    int v = m % VV, b = m / VV;
    float s0 = 0.f, s1 = 0.f;
    int cnt = g_cnt[v];
    for (int j = 0; j < cnt; j++) {
        int nv = g_nbr[v * 8 + j];
        float w = g_w[v * 8 + j];
        const float* p = g_S3 + (size_t)(b * VV + nv) * 3;
        s0 += w * p[0];
        s1 += w * p[1];
    }
    float* o = dout + (size_t)MDIM * HH + (size_t)m * 3;
    o[0] = g_S3[m * 3 + 2] + b15[0];
    o[1] = s0 + b15[1];
    o[2] = s1 + b15[2];
}

// ---------------- driver ----------------------------------------------------
extern "C" void kernel_launch(void* const* d_in, const int* in_sizes, int n_in,
                              void* d_out, int out_size) {
    const float* features = (const float*)d_in[0];
    const float* pooled   = (const float*)d_in[1];
    const float* adj      = (const float*)d_in[2];
    const float* W1       = (const float*)d_in[3];
    const float* b1       = (const float*)d_in[4];
    const float* Wm       = (const float*)d_in[5];
    const float* bm       = (const float*)d_in[6];
    const float* W15      = (const float*)d_in[7];
    const float* b15      = (const float*)d_in[8];
    const float* gamma    = (const float*)d_in[9];
    const float* beta     = (const float*)d_in[10];
    float* dout = (float*)d_out;

    dim3 ggrid(3, (MDIM + 255) / 256);

    adj_kernel<<<(VV + 7) / 8, 256>>>(adj);
    prep_w_kernel<<<(WROWS * HH + 255) / 256, 256>>>(W1, Wm);
    prep_a1_kernel<<<(int)(((size_t)MDIM * (KP_1 / 4) + 255) / 256), 256>>>(features, pooled);

    // layer 1
    gemm_f16_kernel<<<ggrid, 256>>>(2, 0, NT_1);
    post_kernel<<<VV, 256>>>(b1, gamma + 0 * VV, beta + 0 * VV, features, pooled, dout, 0);

    // layer 2
    gemm_f16_kernel<<<ggrid, 256>>>(0, KP_1 + 0 * KP_H, NT_H);
    post_kernel<<<VV, 256>>>(bm + 0 * HH, gamma + 1 * VV, beta + 1 * VV, features, pooled, dout, 1);

    for (int i = 0; i < 5; i++) {
        int wa = 2 * i + 1, wb = 2 * i + 2;
        gemm_f16_kernel<<<ggrid, 256>>>(1, KP_1 + wa * KP_H, NT_H);
        post_kernel<<<VV, 256>>>(bm + wa * HH, gamma + (2 * i + 2) * VV, beta + (2 * i + 2) * VV,
                                 features, pooled, dout, 0);
        gemm_f16_kernel<<<ggrid, 256>>>(0, KP_1 + wb * KP_H, NT_H);
        post_kernel<<<VV, 256>>>(bm + wb * HH, gamma + (2 * i + 3) * VV, beta + (2 * i + 3) * VV,
                                 features, pooled, dout, 2);
    }

    // layer 13
    gemm_f16_kernel<<<ggrid, 256>>>(1, KP_1 + 11 * KP_H, NT_H);
    post_kernel<<<VV, 256>>>(bm + 11 * HH, gamma + 12 * VV, beta + 12 * VV, features, pooled, dout, 3);

    gemm3_kernel<<<(MDIM * 32 + 255) / 256, 256>>>(W15);
    coords_kernel<<<(MDIM + 255) / 256, 256>>>(dout, b15);
}